// round 12
// baseline (speedup 1.0000x reference)
#include <cuda_runtime.h>
#include <cstdint>

#define TSTEPS 16384
#define NBATCH 4
#define HDIM   128
#define NCTA   8
#define NTHR   416
#define WPAD   132

// ---------------- device-global scratch (no runtime allocation) ------------
__device__ float g_hs[TSTEPS * NBATCH * HDIM];   // hidden states [t][b][128]
__device__ float g_M[384 * 4];                   // fused W_ih @ W_embed
__device__ float g_C[384];                       // fused bias (incl. b_ih)
__device__ float g_xq[TSTEPS * 20];              // per-step packed x4 (16) + use_x flag (idx 16)

// ---------------- helpers --------------------------------------------------
__device__ __forceinline__ void fma2(unsigned long long& d, unsigned long long a,
                                     unsigned long long b) {
    asm("fma.rn.f32x2 %0, %1, %2, %0;" : "+l"(d) : "l"(a), "l"(b));
}
__device__ __forceinline__ float f2sum(unsigned long long v) {
    float lo, hi;
    asm("mov.b64 {%0,%1}, %2;" : "=f"(lo), "=f"(hi) : "l"(v));
    return lo + hi;
}
__device__ __forceinline__ float sigm(float x) { return 1.0f / (1.0f + __expf(-x)); }

// ---------------- prep 1: fuse embed into the input-path matvec ------------
__global__ void prep_mc(const float* __restrict__ W_ih, const float* __restrict__ W_embed,
                        const float* __restrict__ b_embed, const float* __restrict__ b_ih) {
    int row = blockIdx.x * blockDim.x + threadIdx.x;
    if (row >= 384) return;
    float m0 = 0.f, m1 = 0.f, m2 = 0.f, m3 = 0.f, c = 0.f;
    for (int k = 0; k < HDIM; k++) {
        float w = W_ih[row * HDIM + k];
        m0 += w * W_embed[k * 4 + 0];
        m1 += w * W_embed[k * 4 + 1];
        m2 += w * W_embed[k * 4 + 2];
        m3 += w * W_embed[k * 4 + 3];
        c  += w * b_embed[k];
    }
    g_M[row * 4 + 0] = m0; g_M[row * 4 + 1] = m1;
    g_M[row * 4 + 2] = m2; g_M[row * 4 + 3] = m3;
    g_C[row] = c + b_ih[row];
}

// ---------------- prep 2: pack per-step inputs -----------------------------
// Reference semantics: x = stack([px,py,vx,vy],0).transpose(0,2,1) -> [4, T, B].
// So model-batch s = SIGNAL index; feature vector for (s, t) is that signal's
// values across the 4 original batches: x[s, t, f] = sig_s[f, t].
__global__ void prep_xq(const float* __restrict__ px, const float* __restrict__ py,
                        const float* __restrict__ vx, const float* __restrict__ vy,
                        const int* __restrict__ mask, const int* __restrict__ cfn) {
    int t = blockIdx.x * blockDim.x + threadIdx.x;
    if (t >= TSTEPS) return;
    int ctx = cfn ? cfn[0] : 8;
    if (ctx < 1) ctx = 1;
    float ux = (t < ctx || mask[t] == 0) ? 1.f : 0.f;
    for (int f = 0; f < 4; f++) {
        g_xq[t * 20 + 0 * 4 + f] = px[f * TSTEPS + t];
        g_xq[t * 20 + 1 * 4 + f] = py[f * TSTEPS + t];
        g_xq[t * 20 + 2 * 4 + f] = vx[f * TSTEPS + t];
        g_xq[t * 20 + 3 * 4 + f] = vy[f * TSTEPS + t];
    }
    g_xq[t * 20 + 16] = ux;
}

// ---------------- sequential GRU: cluster of 8 CTAs ------------------------
// CTA `rank` owns h-columns [16*rank, 16*rank+16). Gate rows (local r48):
//   r48 in [0,48)  -> gh rows (W_hh),  r48 in [48,96) -> gi rows (W_ih).
//   local rr = r48%48: part p = rr/16 (0=r,1=z,2=n), col = rank*16 + rr%16,
//   global gate row grow = p*128 + col.
// 384 dot threads: task = (r48 = tid>>2, b = tid&3). 64 gate threads update h,
// broadcast their slice to all peers via st.shared::cluster, then barrier.cluster.
__global__ void __launch_bounds__(NTHR, 1) __cluster_dims__(NCTA, 1, 1)
gru_seq(const float* __restrict__ W_hh, const float* __restrict__ W_ih,
        const float* __restrict__ b_hh, const float* __restrict__ b_ih) {
    extern __shared__ float sm[];
    float* SW = sm;                    // [96][WPAD] weights
    float* SH = SW + 96 * WPAD;        // [2][4][WPAD] double-buffered h
    float* SP = SH + 8 * WPAD;         // [96][4] dot partials
    float* SX = SP + 96 * 4;           // [2][20] x-stage ring

    int tid = threadIdx.x;
    uint32_t rank;
    asm("mov.u32 %0, %%cluster_ctarank;" : "=r"(rank));

    // ---- init: weights, h=0, first x-stage, per-thread constants ----
    for (int idx = tid; idx < 96 * HDIM; idx += NTHR) {
        int r = idx >> 7, k = idx & 127;
        int rr = r % 48;
        int grow = (rr / 16) * 128 + (int)rank * 16 + (rr % 16);
        const float* src = (r < 48) ? W_hh : W_ih;
        SW[r * WPAD + k] = src[grow * HDIM + k];
    }
    for (int idx = tid; idx < 8 * WPAD; idx += NTHR) SH[idx] = 0.f;
    if (tid < 17) SX[tid] = g_xq[tid];   // stage for t=0 (parity 0)

    int  r48 = tid >> 2, b = tid & 3;
    bool isdot = (tid < 384);
    bool isgi  = isdot && (r48 >= 48);
    float bias = 0.f, m0 = 0.f, m1 = 0.f, m2 = 0.f, m3 = 0.f, cc = 0.f;
    if (isdot) {
        int rr = r48 % 48;
        int grow = (rr / 16) * 128 + (int)rank * 16 + (rr % 16);
        bias = isgi ? b_ih[grow] : b_hh[grow];
        if (isgi) {
            m0 = g_M[grow * 4 + 0]; m1 = g_M[grow * 4 + 1];
            m2 = g_M[grow * 4 + 2]; m3 = g_M[grow * 4 + 3];
            cc = g_C[grow];
        }
    }
    __syncthreads();
    asm volatile("barrier.cluster.arrive.aligned;" ::: "memory");
    asm volatile("barrier.cluster.wait.aligned;" ::: "memory");

    for (int t = 0; t < TSTEPS; t++) {
        int par = t & 1;

        // prefetch next step's packed record (consumed after the barrier)
        float pf = 0.f;
        int pl = tid - 384;
        bool do_pf = (pl >= 0 && pl < 17 && (t + 1) < TSTEPS);
        if (do_pf) pf = g_xq[(t + 1) * 20 + pl];

        // ---- dot phase ----
        if (isdot) {
            float acc;
            float ux = SX[par * 20 + 16];
            if (isgi && ux != 0.f) {
                const float* xv = SX + par * 20 + b * 4;
                acc = cc + m0 * xv[0] + m1 * xv[1] + m2 * xv[2] + m3 * xv[3];
            } else {
                const ulonglong2* wp = (const ulonglong2*)(SW + r48 * WPAD);
                const ulonglong2* hp = (const ulonglong2*)(SH + (par * 4 + b) * WPAD);
                unsigned long long a0 = 0ull, a1 = 0ull;
#pragma unroll
                for (int kk = 0; kk < 32; kk += 2) {
                    ulonglong2 w0 = wp[kk],     h0 = hp[kk];
                    ulonglong2 w1 = wp[kk + 1], h1 = hp[kk + 1];
                    fma2(a0, w0.x, h0.x); fma2(a1, w0.y, h0.y);
                    fma2(a0, w1.x, h1.x); fma2(a1, w1.y, h1.y);
                }
                acc = f2sum(a0) + f2sum(a1) + bias;
            }
            SP[r48 * 4 + b] = acc;
        }
        __syncthreads();

        // ---- gate phase: 64 threads = (jj in 16 cols) x (b in 4) ----
        if (tid < 64) {
            int jj = tid >> 2, bb = tid & 3;
            int col = (int)rank * 16 + jj;
            float rg = sigm(SP[(0  + jj) * 4 + bb] + SP[(48 + jj) * 4 + bb]);
            float zg = sigm(SP[(16 + jj) * 4 + bb] + SP[(64 + jj) * 4 + bb]);
            float ng = tanhf(SP[(80 + jj) * 4 + bb] + rg * SP[(32 + jj) * 4 + bb]);
            float hold = SH[(par * 4 + bb) * WPAD + col];
            float hn = (1.f - zg) * ng + zg * hold;

            int off = ((par ^ 1) * 4 + bb) * WPAD + col;
            SH[off] = hn;  // own copy
            uint32_t laddr = (uint32_t)__cvta_generic_to_shared(SH + off);
#pragma unroll
            for (int peer = 0; peer < NCTA; peer++) {
                if (peer == (int)rank) continue;
                uint32_t raddr;
                asm("mapa.shared::cluster.u32 %0, %1, %2;"
                    : "=r"(raddr) : "r"(laddr), "r"(peer));
                asm volatile("st.shared::cluster.f32 [%0], %1;"
                             :: "r"(raddr), "f"(hn));
            }
            g_hs[(t * NBATCH + bb) * HDIM + col] = hn;
        }

        if (do_pf) SX[(par ^ 1) * 20 + pl] = pf;

        // one barrier/step: release DSMEM writes, CTA-barrier, acquire
        asm volatile("barrier.cluster.arrive.aligned;" ::: "memory");
        asm volatile("barrier.cluster.wait.aligned;" ::: "memory");
    }
}

// ---------------- MLP head over all (t,b) rows -----------------------------
__global__ void __launch_bounds__(256, 1)
head_kernel(const float* __restrict__ W1, const float* __restrict__ b1,
            const float* __restrict__ W2, const float* __restrict__ b2,
            const float* __restrict__ W3, const float* __restrict__ b3,
            float* __restrict__ out) {
    extern __shared__ float s[];
    float* sW1 = s;                 // 64*128
    float* sW2 = sW1 + 64 * 128;    // 64*64
    float* sW3 = sW2 + 64 * 64;     // 2*64
    float* sb1 = sW3 + 128;         // 64
    float* sb2 = sb1 + 64;          // 64
    float* sb3 = sb2 + 64;          // 2
    int tid = threadIdx.x;
    for (int i = tid; i < 64 * 128; i += 256) sW1[i] = W1[i];
    for (int i = tid; i < 64 * 64;  i += 256) sW2[i] = W2[i];
    for (int i = tid; i < 128;      i += 256) sW3[i] = W3[i];
    if (tid < 64) { sb1[tid] = b1[tid]; sb2[tid] = b2[tid]; }
    if (tid < 2)  sb3[tid] = b3[tid];
    __syncthreads();

    int row = blockIdx.x * 256 + tid;       // row = t*4 + b
    float h[128];
    const float4* hp = (const float4*)(g_hs + row * HDIM);
#pragma unroll
    for (int i = 0; i < 32; i++) {
        float4 v = hp[i];
        h[i * 4] = v.x; h[i * 4 + 1] = v.y; h[i * 4 + 2] = v.z; h[i * 4 + 3] = v.w;
    }
    float y1[64];
    for (int o = 0; o < 64; o++) {
        float acc = sb1[o];
        const float4* wp = (const float4*)(sW1 + o * 128);
#pragma unroll
        for (int i = 0; i < 32; i++) {
            float4 w = wp[i];
            acc += w.x * h[i * 4] + w.y * h[i * 4 + 1] + w.z * h[i * 4 + 2] + w.w * h[i * 4 + 3];
        }
        y1[o] = acc > 0.f ? acc : expm1f(acc);
    }
    float y2[64];
    for (int o = 0; o < 64; o++) {
        float acc = sb2[o];
        const float4* wp = (const float4*)(sW2 + o * 64);
#pragma unroll
        for (int i = 0; i < 16; i++) {
            float4 w = wp[i];
            acc += w.x * y1[i * 4] + w.y * y1[i * 4 + 1] + w.z * y1[i * 4 + 2] + w.w * y1[i * 4 + 3];
        }
        y2[o] = acc > 0.f ? acc : expm1f(acc);
    }
    float o0 = sb3[0], o1 = sb3[1];
#pragma unroll
    for (int k = 0; k < 64; k++) {
        o0 += sW3[k] * y2[k];
        o1 += sW3[64 + k] * y2[k];
    }
    int t = row >> 2, bb = row & 3;
    out[bb * TSTEPS + t] = o0;
    out[NBATCH * TSTEPS + bb * TSTEPS + t] = o1;
}

// ---------------- launch ---------------------------------------------------
extern "C" void kernel_launch(void* const* d_in, const int* in_sizes, int n_in,
                              void* d_out, int out_size) {
    const float* pos_x   = (const float*)d_in[0];
    const float* pos_y   = (const float*)d_in[1];
    const float* v_x     = (const float*)d_in[2];
    const float* v_y     = (const float*)d_in[3];
    const float* W_embed = (const float*)d_in[4];
    const float* b_embed = (const float*)d_in[5];
    const float* W_ih    = (const float*)d_in[6];
    const float* W_hh    = (const float*)d_in[7];
    const float* b_ih    = (const float*)d_in[8];
    const float* b_hh    = (const float*)d_in[9];
    const float* W1      = (const float*)d_in[10];
    const float* b1      = (const float*)d_in[11];
    const float* W2      = (const float*)d_in[12];
    const float* b2      = (const float*)d_in[13];
    const float* W3      = (const float*)d_in[14];
    const float* b3      = (const float*)d_in[15];
    const int*   mask    = (const int*)d_in[16];
    const int*   cfn     = (n_in > 17) ? (const int*)d_in[17] : nullptr;
    float* out = (float*)d_out;

    const int seq_smem  = (96 * WPAD + 8 * WPAD + 96 * 4 + 2 * 20) * 4;  // 56,608 B
    const int head_smem = (64 * 128 + 64 * 64 + 128 + 64 + 64 + 2) * 4;  // 50,184 B
    cudaFuncSetAttribute(gru_seq, cudaFuncAttributeMaxDynamicSharedMemorySize, seq_smem);
    cudaFuncSetAttribute(head_kernel, cudaFuncAttributeMaxDynamicSharedMemorySize, head_smem);

    prep_mc<<<3, 128>>>(W_ih, W_embed, b_embed, b_ih);
    prep_xq<<<(TSTEPS + 255) / 256, 256>>>(pos_x, pos_y, v_x, v_y, mask, cfn);
    gru_seq<<<NCTA, NTHR, seq_smem>>>(W_hh, W_ih, b_hh, b_ih);
    head_kernel<<<(TSTEPS * NBATCH) / 256, 256, head_smem>>>(W1, b1, W2, b2, W3, b3, out);
}